// round 2
// baseline (speedup 1.0000x reference)
#include <cuda_runtime.h>
#include <math.h>

#define N_NODES 100000
#define IN_DIM  128
#define HID     64

// ---------------- scratch (static device globals; no allocation) ----------------
__device__ __align__(16) float g_deg [N_NODES];
__device__ __align__(16) float g_dinv[N_NODES];
__device__ __align__(16) float g_h  [(size_t)N_NODES * HID];   // current hidden
__device__ __align__(16) float g_hw [(size_t)N_NODES * HID];   // h @ W
__device__ __align__(16) float g_agg[(size_t)N_NODES * HID];   // aggregation buffer

// ---------------- degree / dinv ----------------
__global__ void init_deg_kernel(int n) {
    int i = blockIdx.x * blockDim.x + threadIdx.x;
    if (i < n) g_deg[i] = 1.0f;                    // self-loop
}

__global__ void count_deg_kernel(const int* __restrict__ dst, int E) {
    int e = blockIdx.x * blockDim.x + threadIdx.x;
    if (e < E) atomicAdd(&g_deg[dst[e]], 1.0f);
}

__global__ void dinv_kernel(int n) {
    int i = blockIdx.x * blockDim.x + threadIdx.x;
    if (i < n) g_dinv[i] = rsqrtf(g_deg[i]);
}

// ---------------- GEMM: x[N,128] @ W_pre[128,64] + b -> g_h ----------------
// 16 rows per block, 256 threads: thread (r, c4) computes 4 output cols.
__global__ void gemm_pre_kernel(const float* __restrict__ x,
                                const float* __restrict__ W,
                                const float* __restrict__ bias, int n) {
    __shared__ float4 Ws[IN_DIM * 16];   // W as [128][16] float4 = 32 KB
    __shared__ float  As[16 * IN_DIM];   // 16 rows of x = 8 KB

    int t = threadIdx.x;
    const float4* W4 = (const float4*)W;
    #pragma unroll
    for (int i = t; i < IN_DIM * 16; i += 256) Ws[i] = W4[i];

    int row0 = blockIdx.x * 16;
    const int rowF4 = IN_DIM / 4;  // 32
    for (int i = t; i < 16 * rowF4; i += 256) {
        int r = i / rowF4, c = i % rowF4;
        float4 v = make_float4(0.f, 0.f, 0.f, 0.f);
        if (row0 + r < n) v = ((const float4*)(x + (size_t)(row0 + r) * IN_DIM))[c];
        ((float4*)As)[i] = v;
    }
    __syncthreads();

    int r = t >> 4, c4 = t & 15;
    float4 acc = make_float4(0.f, 0.f, 0.f, 0.f);
    #pragma unroll
    for (int k = 0; k < IN_DIM; k++) {
        float a = As[r * IN_DIM + k];
        float4 w = Ws[k * 16 + c4];
        acc.x += a * w.x; acc.y += a * w.y; acc.z += a * w.z; acc.w += a * w.w;
    }
    float4 b = ((const float4*)bias)[c4];
    acc.x += b.x; acc.y += b.y; acc.z += b.z; acc.w += b.w;

    int row = row0 + r;
    if (row < n) ((float4*)(g_h + (size_t)row * HID))[c4] = acc;
}

// ---------------- GEMM: g_h[N,64] @ W[64,64] -> g_hw (no bias) ----------------
__global__ void gemm_layer_kernel(const float* __restrict__ W, int n) {
    __shared__ float4 Ws[HID * 16];   // 16 KB
    __shared__ float  As[16 * HID];   // 4 KB

    int t = threadIdx.x;
    const float4* W4 = (const float4*)W;
    #pragma unroll
    for (int i = t; i < HID * 16; i += 256) Ws[i] = W4[i];

    int row0 = blockIdx.x * 16;
    const int rowF4 = HID / 4;  // 16
    for (int i = t; i < 16 * rowF4; i += 256) {
        int r = i / rowF4, c = i % rowF4;
        float4 v = make_float4(0.f, 0.f, 0.f, 0.f);
        if (row0 + r < n) v = ((const float4*)(g_h + (size_t)(row0 + r) * HID))[c];
        ((float4*)As)[i] = v;
    }
    __syncthreads();

    int r = t >> 4, c4 = t & 15;
    float4 acc = make_float4(0.f, 0.f, 0.f, 0.f);
    #pragma unroll
    for (int k = 0; k < HID; k++) {
        float a = As[r * HID + k];
        float4 w = Ws[k * 16 + c4];
        acc.x += a * w.x; acc.y += a * w.y; acc.z += a * w.z; acc.w += a * w.w;
    }
    int row = row0 + r;
    if (row < n) ((float4*)(g_hw + (size_t)row * HID))[c4] = acc;
}

// ---------------- agg init: agg = hw * dinv^2 + b (self-loop + bias) ----------------
__global__ void init_agg_kernel(const float* __restrict__ bias, int n) {
    int i = blockIdx.x * blockDim.x + threadIdx.x;   // over n*16 float4s
    if (i >= n * 16) return;
    int row = i >> 4, c4 = i & 15;
    float d = g_dinv[row];
    float d2 = d * d;
    float4 v = ((const float4*)g_hw)[i];
    float4 b = ((const float4*)bias)[c4];
    v.x = v.x * d2 + b.x; v.y = v.y * d2 + b.y;
    v.z = v.z * d2 + b.z; v.w = v.w * d2 + b.w;
    ((float4*)g_agg)[i] = v;
}

// ---------------- edge scatter: agg[dst] += hw[src] * dinv[src]*dinv[dst] ----------------
// 16 lanes per edge, each handles one float4 chunk; vector red.v4 to L2.
__global__ void scatter_kernel(const int* __restrict__ src_idx,
                               const int* __restrict__ dst_idx, int E) {
    long long tid = (long long)blockIdx.x * blockDim.x + threadIdx.x;
    int e = (int)(tid >> 4);
    if (e >= E) return;
    int lane = (int)(tid & 15);
    int src = src_idx[e];
    int dst = dst_idx[e];
    float nrm = g_dinv[src] * g_dinv[dst];
    float4 v = ((const float4*)(g_hw + (size_t)src * HID))[lane];
    v.x *= nrm; v.y *= nrm; v.z *= nrm; v.w *= nrm;
    float* p = g_agg + (size_t)dst * HID + lane * 4;
    asm volatile("red.global.add.v4.f32 [%0], {%1, %2, %3, %4};"
                 :: "l"(p), "f"(v.x), "f"(v.y), "f"(v.z), "f"(v.w)
                 : "memory");
}

// ---------------- relu: g_h = max(g_agg, 0) ----------------
__global__ void relu_kernel(int total4) {
    int i = blockIdx.x * blockDim.x + threadIdx.x;
    if (i >= total4) return;
    float4 v = ((const float4*)g_agg)[i];
    v.x = fmaxf(v.x, 0.f); v.y = fmaxf(v.y, 0.f);
    v.z = fmaxf(v.z, 0.f); v.w = fmaxf(v.w, 0.f);
    ((float4*)g_h)[i] = v;
}

// ---------------- finalize: L2-normalize rows of g_agg -> out ----------------
__global__ void finalize_kernel(float* __restrict__ out, int n) {
    int gw = (blockIdx.x * blockDim.x + threadIdx.x) >> 5;   // one warp per row
    int lane = threadIdx.x & 31;
    if (gw >= n) return;
    float2 v = ((const float2*)(g_agg + (size_t)gw * HID))[lane];
    float ss = v.x * v.x + v.y * v.y;
    #pragma unroll
    for (int o = 16; o; o >>= 1) ss += __shfl_xor_sync(0xffffffffu, ss, o);
    float scale = 1.0f / fmaxf(sqrtf(ss), 1e-12f);
    float2 r; r.x = v.x * scale; r.y = v.y * scale;
    ((float2*)(out + (size_t)gw * HID))[lane] = r;
}

// ---------------- host launcher ----------------
extern "C" void kernel_launch(void* const* d_in, const int* in_sizes, int n_in,
                              void* d_out, int out_size) {
    const float* x     = (const float*)d_in[0];
    const int*   ei    = (const int*)d_in[1];   // JAX demotes int64 -> int32 (x64 disabled)
    const float* W_pre = (const float*)d_in[2];
    const float* b_pre = (const float*)d_in[3];
    const float* Wl[3] = {(const float*)d_in[4], (const float*)d_in[6], (const float*)d_in[8]};
    const float* Bl[3] = {(const float*)d_in[5], (const float*)d_in[7], (const float*)d_in[9]};
    float* out = (float*)d_out;

    int n = in_sizes[0] / IN_DIM;          // 100000
    int E = in_sizes[1] / 2;               // 1600000
    const int* src_idx = ei;               // edge_index[0]
    const int* dst_idx = ei + E;           // edge_index[1]

    // degree / dinv (recomputed each launch: graph-replay determinism)
    init_deg_kernel<<<(n + 255) / 256, 256>>>(n);
    count_deg_kernel<<<(E + 255) / 256, 256>>>(dst_idx, E);
    dinv_kernel<<<(n + 255) / 256, 256>>>(n);

    // feature_pre linear
    gemm_pre_kernel<<<(n + 15) / 16, 256>>>(x, W_pre, b_pre, n);

    int total4 = n * (HID / 4);
    unsigned scatter_blocks = (unsigned)(((long long)E * 16 + 255) / 256);

    for (int l = 0; l < 3; l++) {
        gemm_layer_kernel<<<(n + 15) / 16, 256>>>(Wl[l], n);
        init_agg_kernel<<<(total4 + 255) / 256, 256>>>(Bl[l], n);
        scatter_kernel<<<scatter_blocks, 256>>>(src_idx, dst_idx, E);
        if (l < 2) {
            relu_kernel<<<(total4 + 255) / 256, 256>>>(total4);
        } else {
            finalize_kernel<<<(n * 32 + 255) / 256, 256>>>(out, n);
        }
    }
}

// round 4
// speedup vs baseline: 1.3223x; 1.3223x over previous
#include <cuda_runtime.h>
#include <math.h>

#define IN_DIM 128
#define HID    64
#define MAXN   100000
#define MAXE   1600000

// ---------------- scratch (static device globals; no allocation) ----------------
__device__ __align__(16) float g_h [(size_t)MAXN * HID];   // layer input
__device__ __align__(16) float g_hw[(size_t)MAXN * HID];   // h @ W
__device__ float g_dinv[MAXN];
__device__ int   g_cnt[MAXN];       // in-degree (without self loop)
__device__ int   g_base[MAXN];      // CSR row start
__device__ int   g_cursor[MAXN];    // fill cursor
__device__ int   g_total;           // atomic allocation counter
__device__ int   g_csr_src [MAXE];  // src node per CSR slot
__device__ float g_csr_dinv[MAXE];  // dinv[src] per CSR slot

// ================= CSR build (scan-free: atomic row allocation) =================
__global__ void zero_cnt_kernel(int n) {
    int i = blockIdx.x * blockDim.x + threadIdx.x;
    if (i < n) g_cnt[i] = 0;
    if (i == 0) g_total = 0;
}

__global__ void hist_kernel(const int* __restrict__ dst, int E) {
    int e = blockIdx.x * blockDim.x + threadIdx.x;
    if (e < E) atomicAdd(&g_cnt[dst[e]], 1);
}

__global__ void alloc_base_kernel(int n) {
    int i = blockIdx.x * blockDim.x + threadIdx.x;
    if (i >= n) return;
    int c = g_cnt[i];
    int base = atomicAdd(&g_total, c);   // contiguous row, arbitrary placement
    g_base[i]   = base;
    g_cursor[i] = base;
    g_dinv[i]   = rsqrtf((float)c + 1.0f);   // deg of A+I
}

__global__ void fill_kernel(const int* __restrict__ src,
                            const int* __restrict__ dst, int E) {
    int e = blockIdx.x * blockDim.x + threadIdx.x;
    if (e >= E) return;
    int d = dst[e];
    int s = src[e];
    int pos = atomicAdd(&g_cursor[d], 1);
    g_csr_src[pos]  = s;
    g_csr_dinv[pos] = g_dinv[s];
}

// ================= GEMMs (R2-proven versions, byte-for-byte) =================
// x[N,128] @ W_pre[128,64] + b -> g_h
__global__ void gemm_pre_kernel(const float* __restrict__ x,
                                const float* __restrict__ W,
                                const float* __restrict__ bias, int n) {
    __shared__ float4 Ws[IN_DIM * 16];   // 32 KB
    __shared__ float  As[16 * IN_DIM];   // 8 KB

    int t = threadIdx.x;
    const float4* W4 = (const float4*)W;
    #pragma unroll
    for (int i = t; i < IN_DIM * 16; i += 256) Ws[i] = W4[i];

    int row0 = blockIdx.x * 16;
    const int rowF4 = IN_DIM / 4;  // 32
    for (int i = t; i < 16 * rowF4; i += 256) {
        int r = i / rowF4, c = i % rowF4;
        float4 v = make_float4(0.f, 0.f, 0.f, 0.f);
        if (row0 + r < n) v = ((const float4*)(x + (size_t)(row0 + r) * IN_DIM))[c];
        ((float4*)As)[i] = v;
    }
    __syncthreads();

    int r = t >> 4, c4 = t & 15;
    float4 acc = make_float4(0.f, 0.f, 0.f, 0.f);
    #pragma unroll
    for (int k = 0; k < IN_DIM; k++) {
        float a = As[r * IN_DIM + k];
        float4 w = Ws[k * 16 + c4];
        acc.x += a * w.x; acc.y += a * w.y; acc.z += a * w.z; acc.w += a * w.w;
    }
    float4 b = ((const float4*)bias)[c4];
    acc.x += b.x; acc.y += b.y; acc.z += b.z; acc.w += b.w;

    int row = row0 + r;
    if (row < n) ((float4*)(g_h + (size_t)row * HID))[c4] = acc;
}

// g_h[N,64] @ W[64,64] -> g_hw (no bias)
__global__ void gemm_layer_kernel(const float* __restrict__ W, int n) {
    __shared__ float4 Ws[HID * 16];   // 16 KB
    __shared__ float  As[16 * HID];   // 4 KB

    int t = threadIdx.x;
    const float4* W4 = (const float4*)W;
    #pragma unroll
    for (int i = t; i < HID * 16; i += 256) Ws[i] = W4[i];

    int row0 = blockIdx.x * 16;
    const int rowF4 = HID / 4;  // 16
    for (int i = t; i < 16 * rowF4; i += 256) {
        int r = i / rowF4, c = i % rowF4;
        float4 v = make_float4(0.f, 0.f, 0.f, 0.f);
        if (row0 + r < n) v = ((const float4*)(g_h + (size_t)(row0 + r) * HID))[c];
        ((float4*)As)[i] = v;
    }
    __syncthreads();

    int r = t >> 4, c4 = t & 15;
    float4 acc = make_float4(0.f, 0.f, 0.f, 0.f);
    #pragma unroll
    for (int k = 0; k < HID; k++) {
        float a = As[r * HID + k];
        float4 w = Ws[k * 16 + c4];
        acc.x += a * w.x; acc.y += a * w.y; acc.z += a * w.z; acc.w += a * w.w;
    }
    int row = row0 + r;
    if (row < n) ((float4*)(g_hw + (size_t)row * HID))[c4] = acc;
}

// ================= fused gather (warp per node) =================
// acc = hw[node]*dinv^2 + b  +  sum_{e: dst=node} hw[src_e] * dinv[src_e]*dinv[node]
// epilogue: RELU -> g_h   or   L2-normalize -> out
template<bool FINAL>
__global__ void gather_kernel(const float* __restrict__ bias,
                              float* __restrict__ out, int n) {
    int w    = (blockIdx.x * blockDim.x + threadIdx.x) >> 5;
    int lane = threadIdx.x & 31;
    if (w >= n) return;

    const float2* hw2 = (const float2*)g_hw;
    float dd = g_dinv[w];
    float2 self = hw2[(size_t)w * 32 + lane];
    float2 b    = ((const float2*)bias)[lane];
    float2 acc;
    acc.x = self.x * dd * dd + b.x;
    acc.y = self.y * dd * dd + b.y;

    int jbeg = g_base[w];
    int jend = jbeg + g_cnt[w];
    for (int j0 = jbeg; j0 < jend; j0 += 32) {
        int j = j0 + lane;
        int   s  = 0;
        float dv = 0.f;
        if (j < jend) { s = g_csr_src[j]; dv = g_csr_dinv[j]; }
        int m = min(32, jend - j0);
        for (int i = 0; i < m; i++) {
            int   si  = __shfl_sync(0xffffffffu, s,  i);
            float nrm = __shfl_sync(0xffffffffu, dv, i) * dd;
            float2 v = hw2[(size_t)si * 32 + lane];
            acc.x += v.x * nrm;
            acc.y += v.y * nrm;
        }
    }

    if (!FINAL) {
        float2 r;
        r.x = fmaxf(acc.x, 0.f);
        r.y = fmaxf(acc.y, 0.f);
        ((float2*)g_h)[(size_t)w * 32 + lane] = r;
    } else {
        float ss = acc.x * acc.x + acc.y * acc.y;
        #pragma unroll
        for (int o = 16; o; o >>= 1) ss += __shfl_xor_sync(0xffffffffu, ss, o);
        float sc = 1.0f / fmaxf(sqrtf(ss), 1e-12f);
        float2 r; r.x = acc.x * sc; r.y = acc.y * sc;
        ((float2*)out)[(size_t)w * 32 + lane] = r;
    }
}

// ================= host launcher =================
extern "C" void kernel_launch(void* const* d_in, const int* in_sizes, int n_in,
                              void* d_out, int out_size) {
    const float* x     = (const float*)d_in[0];
    const int*   ei    = (const int*)d_in[1];   // int32 (JAX x64 disabled)
    const float* W_pre = (const float*)d_in[2];
    const float* b_pre = (const float*)d_in[3];
    const float* Wl[3] = {(const float*)d_in[4], (const float*)d_in[6], (const float*)d_in[8]};
    const float* Bl[3] = {(const float*)d_in[5], (const float*)d_in[7], (const float*)d_in[9]};
    float* out = (float*)d_out;

    int n = in_sizes[0] / IN_DIM;    // 100000
    int E = in_sizes[1] / 2;         // 1600000
    const int* src_idx = ei;
    const int* dst_idx = ei + E;

    // --- CSR build (scan-free) ---
    zero_cnt_kernel<<<(n + 255) / 256, 256>>>(n);
    hist_kernel<<<(E + 255) / 256, 256>>>(dst_idx, E);
    alloc_base_kernel<<<(n + 255) / 256, 256>>>(n);
    fill_kernel<<<(E + 255) / 256, 256>>>(src_idx, dst_idx, E);

    int gemm_blocks   = (n + 15) / 16;
    int gather_blocks = (n * 32 + 255) / 256;

    // feature_pre: x[n,128] @ W_pre + b_pre -> g_h
    gemm_pre_kernel<<<gemm_blocks, 256>>>(x, W_pre, b_pre, n);

    // layer 1
    gemm_layer_kernel<<<gemm_blocks, 256>>>(Wl[0], n);
    gather_kernel<false><<<gather_blocks, 256>>>(Bl[0], nullptr, n);
    // layer 2
    gemm_layer_kernel<<<gemm_blocks, 256>>>(Wl[1], n);
    gather_kernel<false><<<gather_blocks, 256>>>(Bl[1], nullptr, n);
    // layer 3 (+ L2 normalize)
    gemm_layer_kernel<<<gemm_blocks, 256>>>(Wl[2], n);
    gather_kernel<true><<<gather_blocks, 256>>>(Bl[2], out, n);
}

// round 6
// speedup vs baseline: 1.9719x; 1.4913x over previous
#include <cuda_runtime.h>
#include <math.h>

#define IN_DIM 128
#define HID    64
#define MAXN   100000
#define MAXE   1600000

// ---------------- scratch (static device globals; no allocation) ----------------
__device__ __align__(16) float g_h [(size_t)MAXN * HID];   // layer input
__device__ __align__(16) float g_hw[(size_t)MAXN * HID];   // h @ W
__device__ float g_dinv[MAXN];
__device__ int   g_cnt[MAXN];       // in-degree (without self loop)
__device__ int   g_base[MAXN];      // CSR row start
__device__ int   g_cursor[MAXN];    // fill cursor
__device__ int   g_total;           // atomic allocation counter
__device__ int   g_csr_src [MAXE];  // src node per CSR slot
__device__ float g_csr_dinv[MAXE];  // dinv[src] per CSR slot

// ================= CSR build (scan-free: atomic row allocation) =================
__global__ void zero_cnt_kernel(int n) {
    int i = blockIdx.x * blockDim.x + threadIdx.x;
    if (i < n) g_cnt[i] = 0;
    if (i == 0) g_total = 0;
}

__global__ void hist_kernel(const int* __restrict__ dst, int E) {
    int e = blockIdx.x * blockDim.x + threadIdx.x;
    if (e < E) atomicAdd(&g_cnt[dst[e]], 1);
}

__global__ void alloc_base_kernel(int n) {
    int i = blockIdx.x * blockDim.x + threadIdx.x;
    if (i >= n) return;
    int c = g_cnt[i];
    int base = atomicAdd(&g_total, c);   // contiguous row, arbitrary placement
    g_base[i]   = base;
    g_cursor[i] = base;
    g_dinv[i]   = rsqrtf((float)c + 1.0f);   // deg of A+I
}

__global__ void fill_kernel(const int* __restrict__ src,
                            const int* __restrict__ dst, int E) {
    int e = blockIdx.x * blockDim.x + threadIdx.x;
    if (e >= E) return;
    int d = dst[e];
    int s = src[e];
    int pos = atomicAdd(&g_cursor[d], 1);
    g_csr_src[pos]  = s;
    g_csr_dinv[pos] = g_dinv[s];
}

// ================= register-blocked GEMM core =================
// D[64-row tile] = A_tile[64,K] @ W[K,64] (+bias). 256 threads,
// thread (tr,tc): 4 rows x 1 float4 col group -> 16 FMA per 5 LDS.
// A is read via pointer valid IN DEVICE CODE ONLY (global or harness input).
template<int K, bool BIAS>
__device__ __forceinline__ void gemm_rb_body(const float* __restrict__ A,
                                             const float* __restrict__ W,
                                             const float* __restrict__ bias,
                                             float* __restrict__ out, int n) {
    __shared__ float  As[64][68];    // padded stride: rows land in distinct banks
    __shared__ float4 Ws[64][16];

    const int t    = threadIdx.x;
    const int row0 = blockIdx.x * 64;
    const int tr   = (t >> 4) << 2;
    const int tc   = t & 15;

    float4 a0 = make_float4(0.f,0.f,0.f,0.f);
    float4 a1 = a0, a2 = a0, a3 = a0;

    for (int kh = 0; kh < K; kh += 64) {
        #pragma unroll
        for (int i = t; i < 1024; i += 256) {
            int k = i >> 4, c = i & 15;
            Ws[k][c] = ((const float4*)(W + (size_t)(kh + k) * HID))[c];
        }
        #pragma unroll
        for (int i = t; i < 1024; i += 256) {
            int r = i >> 4, c = i & 15;
            float4 v = make_float4(0.f,0.f,0.f,0.f);
            int row = row0 + r;
            if (row < n) v = *(const float4*)(A + (size_t)row * K + kh + c * 4);
            As[r][c*4+0] = v.x; As[r][c*4+1] = v.y;
            As[r][c*4+2] = v.z; As[r][c*4+3] = v.w;
        }
        __syncthreads();

        #pragma unroll 16
        for (int k = 0; k < 64; k++) {
            float4 w = Ws[k][tc];
            float x0 = As[tr+0][k];
            float x1 = As[tr+1][k];
            float x2 = As[tr+2][k];
            float x3 = As[tr+3][k];
            a0.x += x0*w.x; a0.y += x0*w.y; a0.z += x0*w.z; a0.w += x0*w.w;
            a1.x += x1*w.x; a1.y += x1*w.y; a1.z += x1*w.z; a1.w += x1*w.w;
            a2.x += x2*w.x; a2.y += x2*w.y; a2.z += x2*w.z; a2.w += x2*w.w;
            a3.x += x3*w.x; a3.y += x3*w.y; a3.z += x3*w.z; a3.w += x3*w.w;
        }
        __syncthreads();
    }

    if (BIAS) {
        float4 b = ((const float4*)bias)[tc];
        a0.x += b.x; a0.y += b.y; a0.z += b.z; a0.w += b.w;
        a1.x += b.x; a1.y += b.y; a1.z += b.z; a1.w += b.w;
        a2.x += b.x; a2.y += b.y; a2.z += b.z; a2.w += b.w;
        a3.x += b.x; a3.y += b.y; a3.z += b.z; a3.w += b.w;
    }

    if (row0 + tr + 0 < n) ((float4*)(out + (size_t)(row0+tr+0) * HID))[tc] = a0;
    if (row0 + tr + 1 < n) ((float4*)(out + (size_t)(row0+tr+1) * HID))[tc] = a1;
    if (row0 + tr + 2 < n) ((float4*)(out + (size_t)(row0+tr+2) * HID))[tc] = a2;
    if (row0 + tr + 3 < n) ((float4*)(out + (size_t)(row0+tr+3) * HID))[tc] = a3;
}

// Wrappers: device globals are referenced IN DEVICE CODE (never passed from host —
// host-side shadow symbols are host addresses; GB300 ATS dereferences them silently).
__global__ void gemm_pre_rb_kernel(const float* __restrict__ x,
                                   const float* __restrict__ W,
                                   const float* __restrict__ bias, int n) {
    gemm_rb_body<IN_DIM, true>(x, W, bias, g_h, n);
}

__global__ void gemm_layer_rb_kernel(const float* __restrict__ W, int n) {
    gemm_rb_body<HID, false>(g_h, W, nullptr, g_hw, n);
}

// ================= fused gather (warp per node) — proven in R4 =================
// acc = hw[node]*dinv^2 + b  +  sum_{e: dst=node} hw[src_e] * dinv[src_e]*dinv[node]
template<bool FINAL>
__global__ void gather_kernel(const float* __restrict__ bias,
                              float* __restrict__ out, int n) {
    int w    = (blockIdx.x * blockDim.x + threadIdx.x) >> 5;
    int lane = threadIdx.x & 31;
    if (w >= n) return;

    const float2* hw2 = (const float2*)g_hw;
    float dd = g_dinv[w];
    float2 self = hw2[(size_t)w * 32 + lane];
    float2 b    = ((const float2*)bias)[lane];
    float2 acc;
    acc.x = self.x * dd * dd + b.x;
    acc.y = self.y * dd * dd + b.y;

    int jbeg = g_base[w];
    int jend = jbeg + g_cnt[w];
    for (int j0 = jbeg; j0 < jend; j0 += 32) {
        int j = j0 + lane;
        int   s  = 0;
        float dv = 0.f;
        if (j < jend) { s = g_csr_src[j]; dv = g_csr_dinv[j]; }
        int m = min(32, jend - j0);
        for (int i = 0; i < m; i++) {
            int   si  = __shfl_sync(0xffffffffu, s,  i);
            float nrm = __shfl_sync(0xffffffffu, dv, i) * dd;
            float2 v = hw2[(size_t)si * 32 + lane];
            acc.x += v.x * nrm;
            acc.y += v.y * nrm;
        }
    }

    if (!FINAL) {
        float2 r;
        r.x = fmaxf(acc.x, 0.f);
        r.y = fmaxf(acc.y, 0.f);
        ((float2*)g_h)[(size_t)w * 32 + lane] = r;
    } else {
        float ss = acc.x * acc.x + acc.y * acc.y;
        #pragma unroll
        for (int o = 16; o; o >>= 1) ss += __shfl_xor_sync(0xffffffffu, ss, o);
        float sc = 1.0f / fmaxf(sqrtf(ss), 1e-12f);
        float2 r; r.x = acc.x * sc; r.y = acc.y * sc;
        ((float2*)out)[(size_t)w * 32 + lane] = r;
    }
}

// ================= host launcher =================
extern "C" void kernel_launch(void* const* d_in, const int* in_sizes, int n_in,
                              void* d_out, int out_size) {
    const float* x     = (const float*)d_in[0];
    const int*   ei    = (const int*)d_in[1];   // int32 (JAX x64 disabled)
    const float* W_pre = (const float*)d_in[2];
    const float* b_pre = (const float*)d_in[3];
    const float* Wl[3] = {(const float*)d_in[4], (const float*)d_in[6], (const float*)d_in[8]};
    const float* Bl[3] = {(const float*)d_in[5], (const float*)d_in[7], (const float*)d_in[9]};
    float* out = (float*)d_out;

    int n = in_sizes[0] / IN_DIM;    // 100000
    int E = in_sizes[1] / 2;         // 1600000
    const int* src_idx = ei;
    const int* dst_idx = ei + E;

    // --- CSR build (scan-free) ---
    zero_cnt_kernel<<<(n + 255) / 256, 256>>>(n);
    hist_kernel<<<(E + 255) / 256, 256>>>(dst_idx, E);
    alloc_base_kernel<<<(n + 255) / 256, 256>>>(n);
    fill_kernel<<<(E + 255) / 256, 256>>>(src_idx, dst_idx, E);

    int gemm_blocks   = (n + 63) / 64;
    int gather_blocks = (n * 32 + 255) / 256;

    // feature_pre: x[n,128] @ W_pre + b_pre -> g_h
    gemm_pre_rb_kernel<<<gemm_blocks, 256>>>(x, W_pre, b_pre, n);

    // layer 1
    gemm_layer_rb_kernel<<<gemm_blocks, 256>>>(Wl[0], n);
    gather_kernel<false><<<gather_blocks, 256>>>(Bl[0], nullptr, n);
    // layer 2
    gemm_layer_rb_kernel<<<gemm_blocks, 256>>>(Wl[1], n);
    gather_kernel<false><<<gather_blocks, 256>>>(Bl[1], nullptr, n);
    // layer 3 (+ L2 normalize)
    gemm_layer_rb_kernel<<<gemm_blocks, 256>>>(Wl[2], n);
    gather_kernel<true><<<gather_blocks, 256>>>(Bl[2], out, n);
}

// round 8
// speedup vs baseline: 2.0618x; 1.0456x over previous
#include <cuda_runtime.h>
#include <cuda_fp16.h>
#include <math.h>

#define IN_DIM 128
#define HID    64
#define MAXN   100000
#define MAXE   1600000

// ---------------- scratch (static device globals; no allocation) ----------------
__device__ __align__(16) float  g_h   [(size_t)MAXN * HID];  // layer input (fp32)
__device__ __align__(16) __half g_hw_h[(size_t)MAXN * HID];  // h @ W (fp16 storage)
__device__ float g_dinv[MAXN];
__device__ int   g_cnt[MAXN];        // in-degree (without self loop)
__device__ int   g_base[MAXN];       // CSR row start
__device__ int   g_cursor[MAXN];     // fill cursor
__device__ int   g_total;            // atomic allocation counter
__device__ __align__(16) int2 g_csr[MAXE];  // (src, dinv[src] bits) per CSR slot

// ================= CSR build (scan-free: atomic row allocation) =================
__global__ void zero_cnt_kernel(int n) {
    int i = blockIdx.x * blockDim.x + threadIdx.x;
    if (i < n) g_cnt[i] = 0;
    if (i == 0) g_total = 0;
}

__global__ void hist_kernel(const int* __restrict__ dst, int E) {
    int e = blockIdx.x * blockDim.x + threadIdx.x;
    if (e < E) atomicAdd(&g_cnt[dst[e]], 1);
}

__global__ void alloc_base_kernel(int n) {
    int i = blockIdx.x * blockDim.x + threadIdx.x;
    if (i >= n) return;
    int c = g_cnt[i];
    int base = atomicAdd(&g_total, c);   // contiguous row, arbitrary placement
    g_base[i]   = base;
    g_cursor[i] = base;
    g_dinv[i]   = rsqrtf((float)c + 1.0f);   // deg of A+I
}

__global__ void fill_kernel(const int* __restrict__ src,
                            const int* __restrict__ dst, int E) {
    int e = blockIdx.x * blockDim.x + threadIdx.x;
    if (e >= E) return;
    int d = dst[e];
    int s = src[e];
    int pos = atomicAdd(&g_cursor[d], 1);
    g_csr[pos] = make_int2(s, __float_as_int(g_dinv[s]));   // one 8B store
}

// ================= register-blocked GEMM core (proven R6 math) =================
// 64-row tiles, 256 threads, thread = 4 rows x 1 float4 col group.
template<int K>
__device__ __forceinline__ void gemm_rb_compute(const float* __restrict__ A,
                                                const float* __restrict__ W,
                                                int n, int row0,
                                                float4& a0, float4& a1,
                                                float4& a2, float4& a3) {
    __shared__ float  As[64][68];
    __shared__ float4 Ws[64][16];

    const int t  = threadIdx.x;
    const int tr = (t >> 4) << 2;
    const int tc = t & 15;

    for (int kh = 0; kh < K; kh += 64) {
        #pragma unroll
        for (int i = t; i < 1024; i += 256) {
            int k = i >> 4, c = i & 15;
            Ws[k][c] = ((const float4*)(W + (size_t)(kh + k) * HID))[c];
        }
        #pragma unroll
        for (int i = t; i < 1024; i += 256) {
            int r = i >> 4, c = i & 15;
            float4 v = make_float4(0.f,0.f,0.f,0.f);
            int row = row0 + r;
            if (row < n) v = *(const float4*)(A + (size_t)row * K + kh + c * 4);
            As[r][c*4+0] = v.x; As[r][c*4+1] = v.y;
            As[r][c*4+2] = v.z; As[r][c*4+3] = v.w;
        }
        __syncthreads();

        #pragma unroll 16
        for (int k = 0; k < 64; k++) {
            float4 w = Ws[k][tc];
            float x0 = As[tr+0][k];
            float x1 = As[tr+1][k];
            float x2 = As[tr+2][k];
            float x3 = As[tr+3][k];
            a0.x += x0*w.x; a0.y += x0*w.y; a0.z += x0*w.z; a0.w += x0*w.w;
            a1.x += x1*w.x; a1.y += x1*w.y; a1.z += x1*w.z; a1.w += x1*w.w;
            a2.x += x2*w.x; a2.y += x2*w.y; a2.z += x2*w.z; a2.w += x2*w.w;
            a3.x += x3*w.x; a3.y += x3*w.y; a3.z += x3*w.z; a3.w += x3*w.w;
        }
        __syncthreads();
    }
}

// feature_pre: x[n,128] @ W_pre + b -> g_h (fp32 out). Globals referenced in
// device code only (GB300 ATS silently dereferences host shadow symbols).
__global__ void gemm_pre_rb_kernel(const float* __restrict__ x,
                                   const float* __restrict__ W,
                                   const float* __restrict__ bias, int n) {
    float4 a0 = make_float4(0.f,0.f,0.f,0.f), a1 = a0, a2 = a0, a3 = a0;
    int row0 = blockIdx.x * 64;
    gemm_rb_compute<IN_DIM>(x, W, n, row0, a0, a1, a2, a3);

    const int tr = (threadIdx.x >> 4) << 2, tc = threadIdx.x & 15;
    float4 b = ((const float4*)bias)[tc];
    a0.x += b.x; a0.y += b.y; a0.z += b.z; a0.w += b.w;
    a1.x += b.x; a1.y += b.y; a1.z += b.z; a1.w += b.w;
    a2.x += b.x; a2.y += b.y; a2.z += b.z; a2.w += b.w;
    a3.x += b.x; a3.y += b.y; a3.z += b.z; a3.w += b.w;

    if (row0 + tr + 0 < n) ((float4*)(g_h + (size_t)(row0+tr+0) * HID))[tc] = a0;
    if (row0 + tr + 1 < n) ((float4*)(g_h + (size_t)(row0+tr+1) * HID))[tc] = a1;
    if (row0 + tr + 2 < n) ((float4*)(g_h + (size_t)(row0+tr+2) * HID))[tc] = a2;
    if (row0 + tr + 3 < n) ((float4*)(g_h + (size_t)(row0+tr+3) * HID))[tc] = a3;
}

// layer GEMM: g_h[n,64] @ W -> g_hw_h (fp16 storage for gather bandwidth)
__global__ void gemm_layer_rb_kernel(const float* __restrict__ W, int n) {
    float4 a0 = make_float4(0.f,0.f,0.f,0.f), a1 = a0, a2 = a0, a3 = a0;
    int row0 = blockIdx.x * 64;
    gemm_rb_compute<HID>(g_h, W, n, row0, a0, a1, a2, a3);

    const int tr = (threadIdx.x >> 4) << 2, tc = threadIdx.x & 15;
    float4 accs[4] = {a0, a1, a2, a3};
    #pragma unroll
    for (int j = 0; j < 4; j++) {
        int row = row0 + tr + j;
        if (row < n) {
            __half2 h0 = __floats2half2_rn(accs[j].x, accs[j].y);
            __half2 h1 = __floats2half2_rn(accs[j].z, accs[j].w);
            uint2 pack = make_uint2(*reinterpret_cast<const unsigned*>(&h0),
                                    *reinterpret_cast<const unsigned*>(&h1));
            ((uint2*)(g_hw_h + (size_t)row * HID))[tc] = pack;  // 8B per thread
        }
    }
}

// ================= fused gather (warp per node) =================
// acc = hw[node]*dinv^2 + b  +  sum_{e: dst=node} hw[src_e]*dinv[src_e]*dinv[node]
// hw rows are fp16 (128 B/row); accumulation in fp32.
template<bool FINAL>
__global__ void gather_kernel(const float* __restrict__ bias,
                              float* __restrict__ out, int n) {
    int w    = (blockIdx.x * blockDim.x + threadIdx.x) >> 5;
    int lane = threadIdx.x & 31;
    if (w >= n) return;

    const __half2* hw2 = (const __half2*)g_hw_h;   // row = 32 half2
    float dd = g_dinv[w];
    float2 self = __half22float2(hw2[(size_t)w * 32 + lane]);
    float2 b    = ((const float2*)bias)[lane];
    float2 acc;
    acc.x = self.x * dd * dd + b.x;
    acc.y = self.y * dd * dd + b.y;

    int jbeg = g_base[w];
    int jend = jbeg + g_cnt[w];
    for (int j0 = jbeg; j0 < jend; j0 += 32) {
        int j = j0 + lane;
        int   s  = 0;
        float dv = 0.f;
        if (j < jend) {
            int2 rec = g_csr[j];
            s  = rec.x;
            dv = __int_as_float(rec.y);
        }
        int m = min(32, jend - j0);
        for (int i = 0; i < m; i++) {
            int   si  = __shfl_sync(0xffffffffu, s,  i);
            float nrm = __shfl_sync(0xffffffffu, dv, i) * dd;
            float2 v = __half22float2(hw2[(size_t)si * 32 + lane]);
            acc.x += v.x * nrm;
            acc.y += v.y * nrm;
        }
    }

    if (!FINAL) {
        float2 r;
        r.x = fmaxf(acc.x, 0.f);
        r.y = fmaxf(acc.y, 0.f);
        ((float2*)g_h)[(size_t)w * 32 + lane] = r;
    } else {
        float ss = acc.x * acc.x + acc.y * acc.y;
        #pragma unroll
        for (int o = 16; o; o >>= 1) ss += __shfl_xor_sync(0xffffffffu, ss, o);
        float sc = 1.0f / fmaxf(sqrtf(ss), 1e-12f);
        float2 r; r.x = acc.x * sc; r.y = acc.y * sc;
        ((float2*)out)[(size_t)w * 32 + lane] = r;
    }
}

// ================= host launcher =================
extern "C" void kernel_launch(void* const* d_in, const int* in_sizes, int n_in,
                              void* d_out, int out_size) {
    const float* x     = (const float*)d_in[0];
    const int*   ei    = (const int*)d_in[1];   // int32 (JAX x64 disabled)
    const float* W_pre = (const float*)d_in[2];
    const float* b_pre = (const float*)d_in[3];
    const float* Wl[3] = {(const float*)d_in[4], (const float*)d_in[6], (const float*)d_in[8]};
    const float* Bl[3] = {(const float*)d_in[5], (const float*)d_in[7], (const float*)d_in[9]};
    float* out = (float*)d_out;

    int n = in_sizes[0] / IN_DIM;    // 100000
    int E = in_sizes[1] / 2;         // 1600000
    const int* src_idx = ei;
    const int* dst_idx = ei + E;

    // --- CSR build (scan-free) ---
    zero_cnt_kernel<<<(n + 255) / 256, 256>>>(n);
    hist_kernel<<<(E + 255) / 256, 256>>>(dst_idx, E);
    alloc_base_kernel<<<(n + 255) / 256, 256>>>(n);
    fill_kernel<<<(E + 255) / 256, 256>>>(src_idx, dst_idx, E);

    int gemm_blocks   = (n + 63) / 64;
    int gather_blocks = (n * 32 + 255) / 256;

    // feature_pre: x[n,128] @ W_pre + b_pre -> g_h
    gemm_pre_rb_kernel<<<gemm_blocks, 256>>>(x, W_pre, b_pre, n);

    // layer 1
    gemm_layer_rb_kernel<<<gemm_blocks, 256>>>(Wl[0], n);
    gather_kernel<false><<<gather_blocks, 256>>>(Bl[0], nullptr, n);
    // layer 2
    gemm_layer_rb_kernel<<<gemm_blocks, 256>>>(Wl[1], n);
    gather_kernel<false><<<gather_blocks, 256>>>(Bl[1], nullptr, n);
    // layer 3 (+ L2 normalize)
    gemm_layer_rb_kernel<<<gemm_blocks, 256>>>(Wl[2], n);
    gather_kernel<true><<<gather_blocks, 256>>>(Bl[2], out, n);
}